// round 5
// baseline (speedup 1.0000x reference)
#include <cuda_runtime.h>
#include <cuda_bf16.h>
#include <math.h>
#include <stdint.h>

#define NB   2048
#define NSEQ 49
#define ND   384
#define NH   12
#define NHD  32
#define NROWS (NB*NSEQ)   // 100352

// Scratch (device globals — no allocation allowed)
__device__ float g_q[(size_t)NB*NH*NSEQ*NHD];    // [B,H,S,hd]
__device__ float g_k[(size_t)NB*NH*NSEQ*NHD];
__device__ float g_v[(size_t)NB*NH*NSEQ*NHD];
__device__ float g_att[(size_t)NROWS*ND];        // [B,S,D]

// ===========================================================================
// helpers
// ===========================================================================
__device__ __forceinline__ uint32_t smem_u32(const void* p) {
    uint32_t a;
    asm("{ .reg .u64 t; cvta.to.shared.u64 t, %1; cvt.u32.u64 %0, t; }"
        : "=r"(a) : "l"(p));
    return a;
}
__device__ __forceinline__ void ldsm4(uint32_t* r, uint32_t addr) {
    asm volatile("ldmatrix.sync.aligned.m8n8.x4.shared.b16 {%0,%1,%2,%3}, [%4];"
        : "=r"(r[0]), "=r"(r[1]), "=r"(r[2]), "=r"(r[3]) : "r"(addr));
}
__device__ __forceinline__ void mma16816(float* c, const uint32_t* a, const uint32_t* b) {
    asm volatile("mma.sync.aligned.m16n8k16.row.col.f32.bf16.bf16.f32 "
        "{%0,%1,%2,%3}, {%4,%5,%6,%7}, {%8,%9}, {%0,%1,%2,%3};"
        : "+f"(c[0]), "+f"(c[1]), "+f"(c[2]), "+f"(c[3])
        : "r"(a[0]), "r"(a[1]), "r"(a[2]), "r"(a[3]), "r"(b[0]), "r"(b[1]));
}
#define STS128(a, r0, r1, r2, r3) \
    asm volatile("st.shared.v4.b32 [%0], {%1, %2, %3, %4};" \
                 :: "r"(a), "r"(r0), "r"(r1), "r"(r2), "r"(r3) : "memory")

// split fp32 -> bf16 hi/lo, 8 values -> two uint4 (packed bf16x2)
__device__ __forceinline__ void cvt8_hilo(float4 x0, float4 x1, uint4& hi, uint4& lo) {
    float f[8] = {x0.x, x0.y, x0.z, x0.w, x1.x, x1.y, x1.z, x1.w};
    uint32_t h[8], l[8];
#pragma unroll
    for (int i = 0; i < 8; i++) {
        __nv_bfloat16 hb = __float2bfloat16(f[i]);
        __nv_bfloat16 lb = __float2bfloat16(f[i] - __bfloat162float(hb));
        h[i] = (uint32_t)__bfloat16_as_ushort(hb);
        l[i] = (uint32_t)__bfloat16_as_ushort(lb);
    }
    hi = make_uint4(h[0] | (h[1] << 16), h[2] | (h[3] << 16),
                    h[4] | (h[5] << 16), h[6] | (h[7] << 16));
    lo = make_uint4(l[0] | (l[1] << 16), l[2] | (l[3] << 16),
                    l[4] | (l[5] << 16), l[6] | (l[7] << 16));
}

// ===========================================================================
// HMMA GEMM mainloop: acc[128x128] tile of A[M,384] @ W[N,384]^T, bf16 hi/lo
// 3-product split for ~fp32 accuracy. 256 threads = 8 warps (warp wm=wid>>2
// in {0,1} owns 64 rows; wn=wid&3 owns 32 cols). BK=32, 12 k-steps,
// double-buffered smem.
// smem layout (per buffer, row stride 40 bf16 = 80B):
//   Ah @ 0, Al @ 10240, Bh @ 20480, Bl @ 30720 ; buffer stride 40960.
// ===========================================================================
#define OFF_AL 10240u
#define OFF_BH 20480u
#define OFF_BL 30720u
#define BUFSTRIDE 40960u

__device__ __forceinline__ void gemm_mainloop(
    const float* __restrict__ Abase, const float* __restrict__ Wbase,
    int bm, int bn, int tid, float acc[4][4][4])
{
    extern __shared__ char smem[];
    uint32_t sb = smem_u32(smem);
    int wid = tid >> 5, l = tid & 31;
    int wm = wid >> 2, wn = wid & 3;

    const float* arow = Abase + (size_t)(bm + (tid >> 1)) * 384 + (tid & 1) * 16;
    const float* wrow = Wbase + (size_t)(bn + (tid >> 1)) * 384 + (tid & 1) * 16;
    uint32_t sts_off = (uint32_t)((tid >> 1) * 80 + (tid & 1) * 32);

#pragma unroll
    for (int mi = 0; mi < 4; mi++)
#pragma unroll
        for (int nj = 0; nj < 4; nj++)
#pragma unroll
            for (int r = 0; r < 4; r++) acc[mi][nj][r] = 0.f;

    // fragment addresses (byte offsets within a tile)
    uint32_t a_fo[4], b_fo[2];
#pragma unroll
    for (int mi = 0; mi < 4; mi++) {
        int row = wm * 64 + mi * 16 + (l & 15);
        int col = (l >> 4) << 3;
        a_fo[mi] = (uint32_t)(row * 80 + col * 2);
    }
#pragma unroll
    for (int p = 0; p < 2; p++) {
        int row = wn * 32 + p * 16 + (l & 7) + ((l >> 4) << 3);
        int col = ((l >> 3) & 1) << 3;
        b_fo[p] = (uint32_t)(row * 80 + col * 2);
    }

    float4 pa[4], pb[4];
#pragma unroll
    for (int g = 0; g < 4; g++) {
        pa[g] = *(const float4*)(arow + g * 4);
        pb[g] = *(const float4*)(wrow + g * 4);
    }
    // fill buffer 0
    {
        uint32_t base = sb;
#pragma unroll
        for (int h2 = 0; h2 < 2; h2++) {
            uint4 hi, lo;
            cvt8_hilo(pa[h2 * 2], pa[h2 * 2 + 1], hi, lo);
            STS128(base + sts_off + h2 * 16, hi.x, hi.y, hi.z, hi.w);
            STS128(base + OFF_AL + sts_off + h2 * 16, lo.x, lo.y, lo.z, lo.w);
            cvt8_hilo(pb[h2 * 2], pb[h2 * 2 + 1], hi, lo);
            STS128(base + OFF_BH + sts_off + h2 * 16, hi.x, hi.y, hi.z, hi.w);
            STS128(base + OFF_BL + sts_off + h2 * 16, lo.x, lo.y, lo.z, lo.w);
        }
    }
    __syncthreads();

    for (int kt = 0; kt < 12; kt++) {
        if (kt + 1 < 12) {
            int ko = (kt + 1) * 32;
#pragma unroll
            for (int g = 0; g < 4; g++) {
                pa[g] = *(const float4*)(arow + ko + g * 4);
                pb[g] = *(const float4*)(wrow + ko + g * 4);
            }
        }
        uint32_t cbase = sb + (kt & 1) * BUFSTRIDE;
#pragma unroll
        for (int kk = 0; kk < 2; kk++) {
            uint32_t kof = kk * 16;  // bf16 cols -> *2 bytes
            uint32_t ah[4][4], al_[4][4], bh[2][4], bl_[2][4];
#pragma unroll
            for (int mi = 0; mi < 4; mi++) {
                ldsm4(ah[mi], cbase + a_fo[mi] + kof * 2);
                ldsm4(al_[mi], cbase + OFF_AL + a_fo[mi] + kof * 2);
            }
#pragma unroll
            for (int p = 0; p < 2; p++) {
                ldsm4(bh[p], cbase + OFF_BH + b_fo[p] + kof * 2);
                ldsm4(bl_[p], cbase + OFF_BL + b_fo[p] + kof * 2);
            }
#pragma unroll
            for (int mi = 0; mi < 4; mi++)
#pragma unroll
                for (int nj = 0; nj < 4; nj++)
                    mma16816(acc[mi][nj], ah[mi], &bh[nj >> 1][(nj & 1) * 2]);
#pragma unroll
            for (int mi = 0; mi < 4; mi++)
#pragma unroll
                for (int nj = 0; nj < 4; nj++)
                    mma16816(acc[mi][nj], ah[mi], &bl_[nj >> 1][(nj & 1) * 2]);
#pragma unroll
            for (int mi = 0; mi < 4; mi++)
#pragma unroll
                for (int nj = 0; nj < 4; nj++)
                    mma16816(acc[mi][nj], al_[mi], &bh[nj >> 1][(nj & 1) * 2]);
        }
        if (kt + 1 < 12) {
            uint32_t nbase = sb + ((kt + 1) & 1) * BUFSTRIDE;
#pragma unroll
            for (int h2 = 0; h2 < 2; h2++) {
                uint4 hi, lo;
                cvt8_hilo(pa[h2 * 2], pa[h2 * 2 + 1], hi, lo);
                STS128(nbase + sts_off + h2 * 16, hi.x, hi.y, hi.z, hi.w);
                STS128(nbase + OFF_AL + sts_off + h2 * 16, lo.x, lo.y, lo.z, lo.w);
                cvt8_hilo(pb[h2 * 2], pb[h2 * 2 + 1], hi, lo);
                STS128(nbase + OFF_BH + sts_off + h2 * 16, hi.x, hi.y, hi.z, hi.w);
                STS128(nbase + OFF_BL + sts_off + h2 * 16, lo.x, lo.y, lo.z, lo.w);
            }
        }
        __syncthreads();
    }
}

// ---------------------------------------------------------------------------
// Kernel 1: QKV projection -> scatter to g_q/g_k/g_v [B,H,S,hd], q pre-scaled.
// ---------------------------------------------------------------------------
__global__ void __launch_bounds__(256)
mma_qkv_kernel(const float* __restrict__ A,     // [NROWS,384]
               const float* __restrict__ W,     // [1152,384]
               const float* __restrict__ bias)  // [1152]
{
    int tid = threadIdx.x;
    int bm = blockIdx.y * 128, bn = blockIdx.x * 128;
    float acc[4][4][4];
    gemm_mainloop(A, W, bm, bn, tid, acc);

    int wid = tid >> 5, l = tid & 31;
    int wm = wid >> 2, wn = wid & 3;
    int part = bn / 384;
    int h = ((bn % 384) + wn * 32) >> 5;
    const float scl = (part == 0) ? 0.17677669529663687f : 1.0f;
    float* base = (part == 0) ? g_q : (part == 1) ? g_k : g_v;

#pragma unroll
    for (int mi = 0; mi < 4; mi++) {
#pragma unroll
        for (int nj = 0; nj < 4; nj++) {
            int n = bn + wn * 32 + nj * 8 + (l & 3) * 2;
            int d = nj * 8 + (l & 3) * 2;
            float b0 = bias[n], b1 = bias[n + 1];
#pragma unroll
            for (int rh = 0; rh < 2; rh++) {
                int row = bm + wm * 64 + mi * 16 + (l >> 2) + rh * 8;
                int b = row / 49, s = row - b * 49;
                size_t o = (((size_t)(b * 12 + h) * 49 + s) << 5) + d;
                float2 v;
                v.x = (acc[mi][nj][rh * 2 + 0] + b0) * scl;
                v.y = (acc[mi][nj][rh * 2 + 1] + b1) * scl;
                *(float2*)&base[o] = v;
            }
        }
    }
}

// ---------------------------------------------------------------------------
// Kernel 3: output projection. out = g_att @ w_out^T + b_out.
// ---------------------------------------------------------------------------
__global__ void __launch_bounds__(256)
mma_out_kernel(const float* __restrict__ W,     // [384,384]
               const float* __restrict__ bias,  // [384]
               float* __restrict__ C)           // [NROWS,384]
{
    int tid = threadIdx.x;
    int bm = blockIdx.y * 128, bn = blockIdx.x * 128;
    float acc[4][4][4];
    gemm_mainloop(g_att, W, bm, bn, tid, acc);

    int wid = tid >> 5, l = tid & 31;
    int wm = wid >> 2, wn = wid & 3;
#pragma unroll
    for (int mi = 0; mi < 4; mi++) {
#pragma unroll
        for (int nj = 0; nj < 4; nj++) {
            int n = bn + wn * 32 + nj * 8 + (l & 3) * 2;
            float b0 = bias[n], b1 = bias[n + 1];
#pragma unroll
            for (int rh = 0; rh < 2; rh++) {
                int row = bm + wm * 64 + mi * 16 + (l >> 2) + rh * 8;
                float2 v;
                v.x = acc[mi][nj][rh * 2 + 0] + b0;
                v.y = acc[mi][nj][rh * 2 + 1] + b1;
                *(float2*)&C[(size_t)row * 384 + n] = v;
            }
        }
    }
}

// ---------------------------------------------------------------------------
// Kernel 2: per-(window, head) attention.
// scores elementwise; softmax warp-per-row (shfl reductions); PV float4.
// ---------------------------------------------------------------------------
__global__ void __launch_bounds__(128)
attn_kernel(const float* __restrict__ mask,    // [B,49,49]
            const float* __restrict__ table)   // [169,12]
{
    int bh = blockIdx.x;
    int b = bh / 12, h = bh - b * 12;
    __shared__ __align__(16) float qs[49 * 32];
    __shared__ __align__(16) float ks[49 * 32];
    __shared__ __align__(16) float vs[49 * 32];
    __shared__ float sc[49][52];
    int tid = threadIdx.x;
    int wid = tid >> 5, lid = tid & 31;

    const float4* qg = (const float4*)(g_q + (size_t)bh * 49 * 32);
    const float4* kg = (const float4*)(g_k + (size_t)bh * 49 * 32);
    const float4* vg = (const float4*)(g_v + (size_t)bh * 49 * 32);
    for (int i = tid; i < 392; i += 128) {
        ((float4*)qs)[i] = qg[i];
        ((float4*)ks)[i] = kg[i];
        ((float4*)vs)[i] = vg[i];
    }
    __syncthreads();

    const float* mrow = mask + (size_t)b * 49 * 49;
    for (int e = tid; e < 49 * 49; e += 128) {
        int i = e / 49, j = e - i * 49;
        const float4* qp = (const float4*)(qs + i * 32);
        const float4* kp = (const float4*)(ks + j * 32);
        float a = 0.f;
#pragma unroll
        for (int t = 0; t < 8; t++) {
            float4 x = qp[t], y = kp[t];
            a += x.x * y.x + x.y * y.y + x.z * y.z + x.w * y.w;
        }
        int yi = i / 7, xi = i - yi * 7;
        int yj = j / 7, xj = j - yj * 7;
        int ridx = (yi - yj + 6) * 13 + (xi - xj + 6);
        sc[i][j] = a + table[ridx * 12 + h] + mrow[e];
    }
    __syncthreads();

    // softmax: one warp per row, rows wid, wid+4, ...
    for (int i = wid; i < 49; i += 4) {
        float v0 = sc[i][lid];
        float v1 = (lid < 17) ? sc[i][lid + 32] : -INFINITY;
        float mx = fmaxf(v0, v1);
#pragma unroll
        for (int off = 16; off; off >>= 1)
            mx = fmaxf(mx, __shfl_xor_sync(0xFFFFFFFFu, mx, off));
        float e0 = __expf(v0 - mx);
        float e1 = (lid < 17) ? __expf(v1 - mx) : 0.f;
        float s = e0 + e1;
#pragma unroll
        for (int off = 16; off; off >>= 1)
            s += __shfl_xor_sync(0xFFFFFFFFu, s, off);
        float inv = 1.f / s;
        sc[i][lid] = e0 * inv;
        if (lid < 17) sc[i][lid + 32] = e1 * inv;
    }
    __syncthreads();

    // PV: each thread owns (i, d4) float4 outputs
    float* attp = g_att + (size_t)b * 49 * 384 + h * 32;
    for (int e = tid; e < 392; e += 128) {
        int i = e >> 3, d4 = e & 7;
        float4 a = make_float4(0.f, 0.f, 0.f, 0.f);
#pragma unroll 7
        for (int j = 0; j < 49; j++) {
            float s = sc[i][j];
            float4 v = *(const float4*)&vs[j * 32 + d4 * 4];
            a.x += s * v.x; a.y += s * v.y; a.z += s * v.z; a.w += s * v.w;
        }
        *(float4*)&attp[(size_t)i * 384 + d4 * 4] = a;
    }
}

// ---------------------------------------------------------------------------
extern "C" void kernel_launch(void* const* d_in, const int* in_sizes, int n_in,
                              void* d_out, int out_size)
{
    const float* hidden = (const float*)d_in[0];
    const float* mask   = (const float*)d_in[1];
    const float* w_qkv  = (const float*)d_in[2];
    const float* b_qkv  = (const float*)d_in[3];
    const float* w_out  = (const float*)d_in[4];
    const float* b_out  = (const float*)d_in[5];
    const float* table  = (const float*)d_in[6];
    float* out = (float*)d_out;

    const int SMEM_BYTES = 81920;  // 2 buffers x 4 tiles x 10240
    cudaFuncSetAttribute(mma_qkv_kernel, cudaFuncAttributeMaxDynamicSharedMemorySize, SMEM_BYTES);
    cudaFuncSetAttribute(mma_out_kernel, cudaFuncAttributeMaxDynamicSharedMemorySize, SMEM_BYTES);

    mma_qkv_kernel<<<dim3(1152 / 128, NROWS / 128), 256, SMEM_BYTES>>>(hidden, w_qkv, b_qkv);
    attn_kernel<<<NB * NH, 128>>>(mask, table);
    mma_out_kernel<<<dim3(384 / 128, NROWS / 128), 256, SMEM_BYTES>>>(w_out, b_out, out);
}

// round 6
// speedup vs baseline: 2.5905x; 2.5905x over previous
#include <cuda_runtime.h>
#include <math.h>
#include <stdint.h>

#define NROWS 100352

__device__ float g_q[(size_t)24576*1568];   // [B*H, 49, 32], q pre-scaled
__device__ float g_k[(size_t)24576*1568];
__device__ float g_v[(size_t)24576*1568];
__device__ float g_att[(size_t)NROWS*384];

__device__ __forceinline__ uint32_t smem_u32(const void* p) {
    uint32_t a;
    asm("{ .reg .u64 t; cvta.to.shared.u64 t, %1; cvt.u32.u64 %0, t; }" : "=r"(a) : "l"(p));
    return a;
}
__device__ __forceinline__ uint32_t f2tf(float x) {
    uint32_t r; asm("cvt.rna.tf32.f32 %0, %1;" : "=r"(r) : "f"(x)); return r;
}
__device__ __forceinline__ void mma8(float* c, const uint32_t* a, uint32_t b0, uint32_t b1) {
    asm volatile("mma.sync.aligned.m16n8k8.row.col.f32.tf32.tf32.f32 "
        "{%0,%1,%2,%3}, {%4,%5,%6,%7}, {%8,%9}, {%0,%1,%2,%3};"
        : "+f"(c[0]), "+f"(c[1]), "+f"(c[2]), "+f"(c[3])
        : "r"(a[0]), "r"(a[1]), "r"(a[2]), "r"(a[3]), "r"(b0), "r"(b1));
}
__device__ __forceinline__ void cp16(uint32_t s, const float* g) {
    asm volatile("cp.async.cg.shared.global [%0], [%1], 16;" :: "r"(s), "l"(g));
}

// ===========================================================================
// TF32 GEMM: C[128x128] of A[M,384] @ W[N,384]^T. 8 warps, BK=32, 3-stage
// cp.async, XOR-swizzled 128x32 tiles (conflict-free scalar frag loads).
// ===========================================================================
__device__ __forceinline__ void gemm_tf32(const float* __restrict__ A,
                                          const float* __restrict__ W,
                                          int bm, int bn, float acc[4][4][4])
{
    extern __shared__ float sm[];
    const int tid = threadIdx.x;
    const int l = tid & 31, g = l >> 2, t = l & 3;
    const int wm = (tid >> 5) >> 2, wn = (tid >> 5) & 3;

    const int prow = tid >> 1, pc = (tid & 1) * 16;
    const float* ga = A + (size_t)(bm + prow) * 384 + pc;
    const float* gb = W + (size_t)(bn + prow) * 384 + pc;
    const uint32_t swz = (uint32_t)((prow & 7) << 2);
    const uint32_t sa0 = smem_u32(sm) + (uint32_t)prow * 128;
    const uint32_t sb0 = sa0 + 49152;

#pragma unroll
    for (int mi = 0; mi < 4; mi++)
#pragma unroll
        for (int nj = 0; nj < 4; nj++)
#pragma unroll
            for (int q = 0; q < 4; q++) acc[mi][nj][q] = 0.f;

#define ISSUE(KT) do {                                                        \
    uint32_t off = (uint32_t)((KT) % 3) * 16384;                              \
    const float* pa = ga + (KT) * 32;                                         \
    const float* pb = gb + (KT) * 32;                                         \
    _Pragma("unroll")                                                         \
    for (int u = 0; u < 4; u++) {                                             \
        uint32_t c = ((uint32_t)(pc + 4 * u) ^ swz) * 4;                      \
        cp16(sa0 + off + c, pa + 4 * u);                                      \
        cp16(sb0 + off + c, pb + 4 * u);                                      \
    }                                                                         \
    asm volatile("cp.async.commit_group;" ::: "memory");                      \
} while (0)

    ISSUE(0); ISSUE(1);

    const int xsw = g << 2;
    const int ar = wm * 64 + g, br = wn * 32 + g;

    for (int kt = 0; kt < 12; kt++) {
        if (kt < 11) asm volatile("cp.async.wait_group 1;" ::: "memory");
        else         asm volatile("cp.async.wait_group 0;" ::: "memory");
        __syncthreads();
        if (kt < 10) ISSUE(kt + 2);

        const float* bA = sm + (kt % 3) * 4096;
        const float* bB = sm + 12288 + (kt % 3) * 4096;
#pragma unroll
        for (int kc = 0; kc < 4; kc++) {
            const int c0 = (kc * 8 + t) ^ xsw;
            const int c1 = (kc * 8 + t + 4) ^ xsw;
            uint32_t af[4][4], bf[4][2];
#pragma unroll
            for (int mi = 0; mi < 4; mi++) {
                const float* p = bA + (ar + mi * 16) * 32;
                af[mi][0] = f2tf(p[c0]);
                af[mi][1] = f2tf(p[c0 + 256]);
                af[mi][2] = f2tf(p[c1]);
                af[mi][3] = f2tf(p[c1 + 256]);
            }
#pragma unroll
            for (int nj = 0; nj < 4; nj++) {
                const float* p = bB + (br + nj * 8) * 32;
                bf[nj][0] = f2tf(p[c0]);
                bf[nj][1] = f2tf(p[c1]);
            }
#pragma unroll
            for (int mi = 0; mi < 4; mi++)
#pragma unroll
                for (int nj = 0; nj < 4; nj++)
                    mma8(acc[mi][nj], af[mi], bf[nj][0], bf[nj][1]);
        }
    }
#undef ISSUE
}

// ---------------------------------------------------------------------------
__global__ void __launch_bounds__(256, 2)
mma_qkv_kernel(const float* __restrict__ A, const float* __restrict__ W,
               const float* __restrict__ bias)
{
    int tid = threadIdx.x;
    int bm = blockIdx.y * 128, bn = blockIdx.x * 128;
    float acc[4][4][4];
    gemm_tf32(A, W, bm, bn, acc);

    int l = tid & 31;
    int wm = (tid >> 5) >> 2, wn = (tid >> 5) & 3;
    int part = bn / 384;
    int h = ((bn % 384) + wn * 32) >> 5;
    const float scl = (part == 0) ? 0.17677669529663687f : 1.0f;
    float* base = (part == 0) ? g_q : (part == 1) ? g_k : g_v;

#pragma unroll
    for (int mi = 0; mi < 4; mi++)
#pragma unroll
        for (int nj = 0; nj < 4; nj++) {
            int n = bn + wn * 32 + nj * 8 + (l & 3) * 2;
            int d = nj * 8 + (l & 3) * 2;
            float b0 = bias[n], b1 = bias[n + 1];
#pragma unroll
            for (int rh = 0; rh < 2; rh++) {
                int row = bm + wm * 64 + mi * 16 + (l >> 2) + rh * 8;
                int bb = row / 49, ss = row - bb * 49;
                size_t o = (((size_t)(bb * 12 + h) * 49 + ss) << 5) + d;
                *(float2*)&base[o] = make_float2((acc[mi][nj][rh*2] + b0) * scl,
                                                 (acc[mi][nj][rh*2+1] + b1) * scl);
            }
        }
}

// ---------------------------------------------------------------------------
__global__ void __launch_bounds__(256, 2)
mma_out_kernel(const float* __restrict__ W, const float* __restrict__ bias,
               float* __restrict__ C)
{
    int tid = threadIdx.x;
    int bm = blockIdx.y * 128, bn = blockIdx.x * 128;
    float acc[4][4][4];
    gemm_tf32(g_att, W, bm, bn, acc);

    int l = tid & 31;
    int wm = (tid >> 5) >> 2, wn = (tid >> 5) & 3;
#pragma unroll
    for (int mi = 0; mi < 4; mi++)
#pragma unroll
        for (int nj = 0; nj < 4; nj++) {
            int n = bn + wn * 32 + nj * 8 + (l & 3) * 2;
            float b0 = bias[n], b1 = bias[n + 1];
#pragma unroll
            for (int rh = 0; rh < 2; rh++) {
                int row = bm + wm * 64 + mi * 16 + (l >> 2) + rh * 8;
                *(float2*)&C[(size_t)row * 384 + n] =
                    make_float2(acc[mi][nj][rh*2] + b0, acc[mi][nj][rh*2+1] + b1);
            }
        }
}

// ---------------------------------------------------------------------------
// Attention: one CTA per (b,h). QK^T m64xn56xk32 TF32 MMA; softmax in regs;
// P reuses the bias/mask smem array; PV m64xn32xk56 MMA.
// ---------------------------------------------------------------------------
__global__ void __launch_bounds__(128)
attn_kernel(const float* __restrict__ mask, const float* __restrict__ table)
{
    __shared__ float qs[64 * 36];   // rows >= 49 garbage (rows not stored)
    __shared__ float ks[56 * 36];   // rows >= 49 masked out
    __shared__ float vs[56 * 40];   // rows 49..55 zeroed
    __shared__ float amb[64 * 60];  // bias+mask, then P

    int bh = blockIdx.x;
    int b = bh / 12, h = bh - b * 12;
    int tid = threadIdx.x, w = tid >> 5, l = tid & 31, g = l >> 2, t = l & 3;

    const float4* qg = (const float4*)(g_q + (size_t)bh * 1568);
    const float4* kg = (const float4*)(g_k + (size_t)bh * 1568);
    const float4* vg = (const float4*)(g_v + (size_t)bh * 1568);
    for (int e = tid; e < 392; e += 128) {
        int i = e >> 3, c = (e & 7) * 4;
        *(float4*)&qs[i * 36 + c] = qg[e];
        *(float4*)&ks[i * 36 + c] = kg[e];
        *(float4*)&vs[i * 40 + c] = vg[e];
    }
    for (int e = tid; e < 280; e += 128) vs[1960 + e] = 0.f;
    const float* mrow = mask + (size_t)b * 2401;
    for (int e = tid; e < 2401; e += 128) {
        int i = e / 49, j = e - i * 49;
        int yi = i / 7, xi = i - yi * 7, yj = j / 7, xj = j - yj * 7;
        amb[i * 60 + j] = mrow[e] + table[((yi - yj + 6) * 13 + (xi - xj + 6)) * 12 + h];
    }
    __syncthreads();

    // QK^T
    float s[7][4];
#pragma unroll
    for (int T = 0; T < 7; T++) { s[T][0]=0.f; s[T][1]=0.f; s[T][2]=0.f; s[T][3]=0.f; }
    const int rA = w * 16 + g;
    const int qr = rA * 36;
#pragma unroll
    for (int kc = 0; kc < 4; kc++) {
        int c = kc * 8 + t;
        uint32_t a[4] = { f2tf(qs[qr + c]), f2tf(qs[qr + 288 + c]),
                          f2tf(qs[qr + c + 4]), f2tf(qs[qr + 288 + c + 4]) };
#pragma unroll
        for (int T = 0; T < 7; T++) {
            int kr = (T * 8 + g) * 36;
            mma8(s[T], a, f2tf(ks[kr + c]), f2tf(ks[kr + c + 4]));
        }
    }
    // + bias + mask, j>=49 -> -inf
#pragma unroll
    for (int T = 0; T < 7; T++) {
        int j0 = T * 8 + 2 * t;
        float2 m0 = *(const float2*)&amb[rA * 60 + j0];
        float2 m1 = *(const float2*)&amb[(rA + 8) * 60 + j0];
        s[T][0] = (j0 < 49)     ? s[T][0] + m0.x : -1e30f;
        s[T][1] = (j0 + 1 < 49) ? s[T][1] + m0.y : -1e30f;
        s[T][2] = (j0 < 49)     ? s[T][2] + m1.x : -1e30f;
        s[T][3] = (j0 + 1 < 49) ? s[T][3] + m1.y : -1e30f;
    }
    // softmax (rows rA and rA+8; quad-lane reductions)
    float mA = -1e30f, mB = -1e30f;
#pragma unroll
    for (int T = 0; T < 7; T++) {
        mA = fmaxf(mA, fmaxf(s[T][0], s[T][1]));
        mB = fmaxf(mB, fmaxf(s[T][2], s[T][3]));
    }
    mA = fmaxf(mA, __shfl_xor_sync(~0u, mA, 1)); mA = fmaxf(mA, __shfl_xor_sync(~0u, mA, 2));
    mB = fmaxf(mB, __shfl_xor_sync(~0u, mB, 1)); mB = fmaxf(mB, __shfl_xor_sync(~0u, mB, 2));
    float dA = 0.f, dB = 0.f;
#pragma unroll
    for (int T = 0; T < 7; T++) {
        s[T][0] = __expf(s[T][0] - mA); s[T][1] = __expf(s[T][1] - mA);
        s[T][2] = __expf(s[T][2] - mB); s[T][3] = __expf(s[T][3] - mB);
        dA += s[T][0] + s[T][1]; dB += s[T][2] + s[T][3];
    }
    dA += __shfl_xor_sync(~0u, dA, 1); dA += __shfl_xor_sync(~0u, dA, 2);
    dB += __shfl_xor_sync(~0u, dB, 1); dB += __shfl_xor_sync(~0u, dB, 2);
    float iA = 1.f / dA, iB = 1.f / dB;
#pragma unroll
    for (int T = 0; T < 7; T++) {
        int j0 = T * 8 + 2 * t;
        *(float2*)&amb[rA * 60 + j0]       = make_float2(s[T][0] * iA, s[T][1] * iA);
        *(float2*)&amb[(rA + 8) * 60 + j0] = make_float2(s[T][2] * iB, s[T][3] * iB);
    }
    __syncwarp();

    // PV
    float o[4][4];
#pragma unroll
    for (int nj = 0; nj < 4; nj++) { o[nj][0]=0.f; o[nj][1]=0.f; o[nj][2]=0.f; o[nj][3]=0.f; }
#pragma unroll
    for (int kc = 0; kc < 7; kc++) {
        int c = kc * 8 + t;
        uint32_t a[4] = { f2tf(amb[rA * 60 + c]), f2tf(amb[(rA + 8) * 60 + c]),
                          f2tf(amb[rA * 60 + c + 4]), f2tf(amb[(rA + 8) * 60 + c + 4]) };
#pragma unroll
        for (int nj = 0; nj < 4; nj++)
            mma8(o[nj], a, f2tf(vs[c * 40 + nj * 8 + g]),
                 f2tf(vs[(c + 4) * 40 + nj * 8 + g]));
    }
    float* ap = g_att + (size_t)b * 18816 + h * 32;
#pragma unroll
    for (int nj = 0; nj < 4; nj++) {
        int d = nj * 8 + 2 * t;
        if (rA < 49)
            *(float2*)&ap[(size_t)rA * 384 + d] = make_float2(o[nj][0], o[nj][1]);
        if (rA + 8 < 49)
            *(float2*)&ap[(size_t)(rA + 8) * 384 + d] = make_float2(o[nj][2], o[nj][3]);
    }
}

// ---------------------------------------------------------------------------
extern "C" void kernel_launch(void* const* d_in, const int* in_sizes, int n_in,
                              void* d_out, int out_size)
{
    const float* hidden = (const float*)d_in[0];
    const float* mask   = (const float*)d_in[1];
    const float* w_qkv  = (const float*)d_in[2];
    const float* b_qkv  = (const float*)d_in[3];
    const float* w_out  = (const float*)d_in[4];
    const float* b_out  = (const float*)d_in[5];
    const float* table  = (const float*)d_in[6];
    float* out = (float*)d_out;

    const int SMEM = 98304;  // 6 tiles x 16 KB
    cudaFuncSetAttribute(mma_qkv_kernel, cudaFuncAttributeMaxDynamicSharedMemorySize, SMEM);
    cudaFuncSetAttribute(mma_out_kernel, cudaFuncAttributeMaxDynamicSharedMemorySize, SMEM);

    mma_qkv_kernel<<<dim3(9, 784), 256, SMEM>>>(hidden, w_qkv, b_qkv);
    attn_kernel<<<24576, 128>>>(mask, table);
    mma_out_kernel<<<dim3(3, 784), 256, SMEM>>>(w_out, b_out, out);
}

// round 7
// speedup vs baseline: 2.6900x; 1.0384x over previous
#include <cuda_runtime.h>
#include <math.h>
#include <stdint.h>

#define NROWS 100352

__device__ float g_q[(size_t)24576*1568];   // [B*H, 49, 32], pre-scaled, tf32-rounded
__device__ float g_k[(size_t)24576*1568];
__device__ float g_v[(size_t)24576*1568];
__device__ float g_att[(size_t)NROWS*384];  // tf32-rounded
__device__ float g_hid[(size_t)NROWS*384];  // tf32-rounded hidden
__device__ float g_wq[1152*384];            // tf32-rounded w_qkv
__device__ float g_wo[384*384];             // tf32-rounded w_out
__device__ int   g_ridx[2401];              // rel-pos index * 12

__device__ __forceinline__ uint32_t smem_u32(const void* p) {
    uint32_t a;
    asm("{ .reg .u64 t; cvta.to.shared.u64 t, %1; cvt.u32.u64 %0, t; }" : "=r"(a) : "l"(p));
    return a;
}
__device__ __forceinline__ uint32_t f2tf(float x) {
    uint32_t r; asm("cvt.rna.tf32.f32 %0, %1;" : "=r"(r) : "f"(x)); return r;
}
__device__ __forceinline__ float tf32f(float x) { return __uint_as_float(f2tf(x)); }
__device__ __forceinline__ void mma8(float* c, const uint32_t* a, uint32_t b0, uint32_t b1) {
    asm volatile("mma.sync.aligned.m16n8k8.row.col.f32.tf32.tf32.f32 "
        "{%0,%1,%2,%3}, {%4,%5,%6,%7}, {%8,%9}, {%0,%1,%2,%3};"
        : "+f"(c[0]), "+f"(c[1]), "+f"(c[2]), "+f"(c[3])
        : "r"(a[0]), "r"(a[1]), "r"(a[2]), "r"(a[3]), "r"(b0), "r"(b1));
}
__device__ __forceinline__ void cp16(uint32_t s, const float* g) {
    asm volatile("cp.async.cg.shared.global [%0], [%1], 16;" :: "r"(s), "l"(g));
}

// ---------------------------------------------------------------------------
// Prepass: tf32-round a float array (float4 grid-stride) + ridx table
// ---------------------------------------------------------------------------
__global__ void round_kernel(const float4* __restrict__ src, float4* __restrict__ dst, int n4) {
    int i = blockIdx.x * blockDim.x + threadIdx.x;
    if (i < n4) {
        float4 v = src[i];
        v.x = tf32f(v.x); v.y = tf32f(v.y); v.z = tf32f(v.z); v.w = tf32f(v.w);
        dst[i] = v;
    }
}
__global__ void ridx_kernel() {
    int e = blockIdx.x * blockDim.x + threadIdx.x;
    if (e < 2401) {
        int i = e / 49, j = e - i * 49;
        int yi = i / 7, xi = i - yi * 7, yj = j / 7, xj = j - yj * 7;
        g_ridx[e] = ((yi - yj + 6) * 13 + (xi - xj + 6)) * 12;
    }
}

// ===========================================================================
// TF32 GEMM: C[128x128] of A[M,384] @ W[N,384]^T; inputs pre-rounded to tf32.
// 8 warps, BK=32, 3-stage cp.async, XOR-swizzled tiles, raw-bit frag loads.
// ===========================================================================
__device__ __forceinline__ void gemm_tf32(const float* __restrict__ A,
                                          const float* __restrict__ W,
                                          int bm, int bn, float acc[4][4][4])
{
    extern __shared__ float sm[];
    const int tid = threadIdx.x;
    const int l = tid & 31, g = l >> 2, t = l & 3;
    const int wm = (tid >> 5) >> 2, wn = (tid >> 5) & 3;

    const int prow = tid >> 1, pc = (tid & 1) * 16;
    const float* ga = A + (size_t)(bm + prow) * 384 + pc;
    const float* gb = W + (size_t)(bn + prow) * 384 + pc;
    const uint32_t swz = (uint32_t)((prow & 7) << 2);
    const uint32_t sa0 = smem_u32(sm) + (uint32_t)prow * 128;
    const uint32_t sb0 = sa0 + 49152;

#pragma unroll
    for (int mi = 0; mi < 4; mi++)
#pragma unroll
        for (int nj = 0; nj < 4; nj++)
#pragma unroll
            for (int q = 0; q < 4; q++) acc[mi][nj][q] = 0.f;

#define ISSUE(KT) do {                                                        \
    uint32_t off = (uint32_t)((KT) % 3) * 16384;                              \
    const float* pa = ga + (KT) * 32;                                         \
    const float* pb = gb + (KT) * 32;                                         \
    _Pragma("unroll")                                                         \
    for (int u = 0; u < 4; u++) {                                             \
        uint32_t c = ((uint32_t)(pc + 4 * u) ^ swz) * 4;                      \
        cp16(sa0 + off + c, pa + 4 * u);                                      \
        cp16(sb0 + off + c, pb + 4 * u);                                      \
    }                                                                         \
    asm volatile("cp.async.commit_group;" ::: "memory");                      \
} while (0)

    ISSUE(0); ISSUE(1);

    const int xsw = g << 2;
    const int ar = wm * 64 + g, br = wn * 32 + g;

    for (int kt = 0; kt < 12; kt++) {
        if (kt < 11) asm volatile("cp.async.wait_group 1;" ::: "memory");
        else         asm volatile("cp.async.wait_group 0;" ::: "memory");
        __syncthreads();
        if (kt < 10) ISSUE(kt + 2);

        const float* bA = sm + (kt % 3) * 4096;
        const float* bB = sm + 12288 + (kt % 3) * 4096;
#pragma unroll
        for (int kc = 0; kc < 4; kc++) {
            const int c0 = (kc * 8 + t) ^ xsw;
            const int c1 = (kc * 8 + t + 4) ^ xsw;
            uint32_t af[4][4], bf[4][2];
#pragma unroll
            for (int mi = 0; mi < 4; mi++) {
                const float* p = bA + (ar + mi * 16) * 32;
                af[mi][0] = __float_as_uint(p[c0]);
                af[mi][1] = __float_as_uint(p[c0 + 256]);
                af[mi][2] = __float_as_uint(p[c1]);
                af[mi][3] = __float_as_uint(p[c1 + 256]);
            }
#pragma unroll
            for (int nj = 0; nj < 4; nj++) {
                const float* p = bB + (br + nj * 8) * 32;
                bf[nj][0] = __float_as_uint(p[c0]);
                bf[nj][1] = __float_as_uint(p[c1]);
            }
#pragma unroll
            for (int mi = 0; mi < 4; mi++)
#pragma unroll
                for (int nj = 0; nj < 4; nj++)
                    mma8(acc[mi][nj], af[mi], bf[nj][0], bf[nj][1]);
        }
    }
#undef ISSUE
}

// ---------------------------------------------------------------------------
__global__ void __launch_bounds__(256, 2)
mma_qkv_kernel(const float* __restrict__ bias)
{
    int tid = threadIdx.x;
    int bm = blockIdx.y * 128, bn = blockIdx.x * 128;
    float acc[4][4][4];
    gemm_tf32(g_hid, g_wq, bm, bn, acc);

    int l = tid & 31;
    int wm = (tid >> 5) >> 2, wn = (tid >> 5) & 3;
    int part = bn / 384;
    int h = ((bn % 384) + wn * 32) >> 5;
    const float scl = (part == 0) ? 0.17677669529663687f : 1.0f;
    float* base = (part == 0) ? g_q : (part == 1) ? g_k : g_v;

#pragma unroll
    for (int mi = 0; mi < 4; mi++)
#pragma unroll
        for (int nj = 0; nj < 4; nj++) {
            int n = bn + wn * 32 + nj * 8 + (l & 3) * 2;
            int d = nj * 8 + (l & 3) * 2;
            float b0 = bias[n], b1 = bias[n + 1];
#pragma unroll
            for (int rh = 0; rh < 2; rh++) {
                int row = bm + wm * 64 + mi * 16 + (l >> 2) + rh * 8;
                int bb = row / 49, ss = row - bb * 49;
                size_t o = (((size_t)(bb * 12 + h) * 49 + ss) << 5) + d;
                *(float2*)&base[o] =
                    make_float2(tf32f((acc[mi][nj][rh*2] + b0) * scl),
                                tf32f((acc[mi][nj][rh*2+1] + b1) * scl));
            }
        }
}

// ---------------------------------------------------------------------------
__global__ void __launch_bounds__(256, 2)
mma_out_kernel(const float* __restrict__ bias, float* __restrict__ C)
{
    int tid = threadIdx.x;
    int bm = blockIdx.y * 128, bn = blockIdx.x * 128;
    float acc[4][4][4];
    gemm_tf32(g_att, g_wo, bm, bn, acc);

    int l = tid & 31;
    int wm = (tid >> 5) >> 2, wn = (tid >> 5) & 3;
#pragma unroll
    for (int mi = 0; mi < 4; mi++)
#pragma unroll
        for (int nj = 0; nj < 4; nj++) {
            int n = bn + wn * 32 + nj * 8 + (l & 3) * 2;
            float b0 = bias[n], b1 = bias[n + 1];
#pragma unroll
            for (int rh = 0; rh < 2; rh++) {
                int row = bm + wm * 64 + mi * 16 + (l >> 2) + rh * 8;
                *(float2*)&C[(size_t)row * 384 + n] =
                    make_float2(acc[mi][nj][rh*2] + b0, acc[mi][nj][rh*2+1] + b1);
            }
        }
}

// ---------------------------------------------------------------------------
// Attention: one CTA per (b,h). All MMA inputs pre-rounded -> raw bit loads.
// ---------------------------------------------------------------------------
__global__ void __launch_bounds__(128)
attn_kernel(const float* __restrict__ mask, const float* __restrict__ table)
{
    __shared__ float qs[64 * 36];
    __shared__ float ks[56 * 36];
    __shared__ float vs[56 * 40];
    __shared__ float amb[64 * 60];  // bias+mask, then P (tf32-rounded)

    int bh = blockIdx.x;
    int b = bh / 12, h = bh - b * 12;
    int tid = threadIdx.x, w = tid >> 5, l = tid & 31, g = l >> 2, t = l & 3;

    const float4* qg = (const float4*)(g_q + (size_t)bh * 1568);
    const float4* kg = (const float4*)(g_k + (size_t)bh * 1568);
    const float4* vg = (const float4*)(g_v + (size_t)bh * 1568);
    for (int e = tid; e < 392; e += 128) {
        int i = e >> 3, c = (e & 7) * 4;
        *(float4*)&qs[i * 36 + c] = qg[e];
        *(float4*)&ks[i * 36 + c] = kg[e];
        *(float4*)&vs[i * 40 + c] = vg[e];
    }
    for (int e = tid; e < 280; e += 128) vs[1960 + e] = 0.f;
    const float* mrow = mask + (size_t)b * 2401;
    for (int e = tid; e < 2401; e += 128) {
        int i = e / 49, j = e - i * 49;
        amb[i * 60 + j] = mrow[e] + table[g_ridx[e] + h];
    }
    __syncthreads();

    // QK^T
    float s[7][4];
#pragma unroll
    for (int T = 0; T < 7; T++) { s[T][0]=0.f; s[T][1]=0.f; s[T][2]=0.f; s[T][3]=0.f; }
    const int rA = w * 16 + g;
    const int qr = rA * 36;
#pragma unroll
    for (int kc = 0; kc < 4; kc++) {
        int c = kc * 8 + t;
        uint32_t a[4] = { __float_as_uint(qs[qr + c]), __float_as_uint(qs[qr + 288 + c]),
                          __float_as_uint(qs[qr + c + 4]), __float_as_uint(qs[qr + 288 + c + 4]) };
#pragma unroll
        for (int T = 0; T < 7; T++) {
            int kr = (T * 8 + g) * 36;
            mma8(s[T], a, __float_as_uint(ks[kr + c]), __float_as_uint(ks[kr + c + 4]));
        }
    }
    // + bias + mask, j>=49 -> -inf
#pragma unroll
    for (int T = 0; T < 7; T++) {
        int j0 = T * 8 + 2 * t;
        float2 m0 = *(const float2*)&amb[rA * 60 + j0];
        float2 m1 = *(const float2*)&amb[(rA + 8) * 60 + j0];
        s[T][0] = (j0 < 49)     ? s[T][0] + m0.x : -1e30f;
        s[T][1] = (j0 + 1 < 49) ? s[T][1] + m0.y : -1e30f;
        s[T][2] = (j0 < 49)     ? s[T][2] + m1.x : -1e30f;
        s[T][3] = (j0 + 1 < 49) ? s[T][3] + m1.y : -1e30f;
    }
    // softmax (rows rA, rA+8)
    float mA = -1e30f, mB = -1e30f;
#pragma unroll
    for (int T = 0; T < 7; T++) {
        mA = fmaxf(mA, fmaxf(s[T][0], s[T][1]));
        mB = fmaxf(mB, fmaxf(s[T][2], s[T][3]));
    }
    mA = fmaxf(mA, __shfl_xor_sync(~0u, mA, 1)); mA = fmaxf(mA, __shfl_xor_sync(~0u, mA, 2));
    mB = fmaxf(mB, __shfl_xor_sync(~0u, mB, 1)); mB = fmaxf(mB, __shfl_xor_sync(~0u, mB, 2));
    float dA = 0.f, dB = 0.f;
#pragma unroll
    for (int T = 0; T < 7; T++) {
        s[T][0] = __expf(s[T][0] - mA); s[T][1] = __expf(s[T][1] - mA);
        s[T][2] = __expf(s[T][2] - mB); s[T][3] = __expf(s[T][3] - mB);
        dA += s[T][0] + s[T][1]; dB += s[T][2] + s[T][3];
    }
    dA += __shfl_xor_sync(~0u, dA, 1); dA += __shfl_xor_sync(~0u, dA, 2);
    dB += __shfl_xor_sync(~0u, dB, 1); dB += __shfl_xor_sync(~0u, dB, 2);
    float iA = 1.f / dA, iB = 1.f / dB;
#pragma unroll
    for (int T = 0; T < 7; T++) {
        int j0 = T * 8 + 2 * t;
        *(float2*)&amb[rA * 60 + j0] =
            make_float2(tf32f(s[T][0] * iA), tf32f(s[T][1] * iA));
        *(float2*)&amb[(rA + 8) * 60 + j0] =
            make_float2(tf32f(s[T][2] * iB), tf32f(s[T][3] * iB));
    }
    __syncwarp();

    // PV
    float o[4][4];
#pragma unroll
    for (int nj = 0; nj < 4; nj++) { o[nj][0]=0.f; o[nj][1]=0.f; o[nj][2]=0.f; o[nj][3]=0.f; }
#pragma unroll
    for (int kc = 0; kc < 7; kc++) {
        int c = kc * 8 + t;
        uint32_t a[4] = { __float_as_uint(amb[rA * 60 + c]), __float_as_uint(amb[(rA + 8) * 60 + c]),
                          __float_as_uint(amb[rA * 60 + c + 4]), __float_as_uint(amb[(rA + 8) * 60 + c + 4]) };
#pragma unroll
        for (int nj = 0; nj < 4; nj++)
            mma8(o[nj], a, __float_as_uint(vs[c * 40 + nj * 8 + g]),
                 __float_as_uint(vs[(c + 4) * 40 + nj * 8 + g]));
    }
    float* ap = g_att + (size_t)b * 18816 + h * 32;
#pragma unroll
    for (int nj = 0; nj < 4; nj++) {
        int d = nj * 8 + 2 * t;
        if (rA < 49)
            *(float2*)&ap[(size_t)rA * 384 + d] =
                make_float2(tf32f(o[nj][0]), tf32f(o[nj][1]));
        if (rA + 8 < 49)
            *(float2*)&ap[(size_t)(rA + 8) * 384 + d] =
                make_float2(tf32f(o[nj][2]), tf32f(o[nj][3]));
    }
}

// ---------------------------------------------------------------------------
extern "C" void kernel_launch(void* const* d_in, const int* in_sizes, int n_in,
                              void* d_out, int out_size)
{
    const float* hidden = (const float*)d_in[0];
    const float* mask   = (const float*)d_in[1];
    const float* w_qkv  = (const float*)d_in[2];
    const float* b_qkv  = (const float*)d_in[3];
    const float* w_out  = (const float*)d_in[4];
    const float* b_out  = (const float*)d_in[5];
    const float* table  = (const float*)d_in[6];
    float* out = (float*)d_out;

    float* hid_p; cudaGetSymbolAddress((void**)&hid_p, g_hid);
    float* wq_p;  cudaGetSymbolAddress((void**)&wq_p,  g_wq);
    float* wo_p;  cudaGetSymbolAddress((void**)&wo_p,  g_wo);

    round_kernel<<<(NROWS*384/4 + 255)/256, 256>>>((const float4*)hidden, (float4*)hid_p, NROWS*384/4);
    round_kernel<<<(1152*384/4 + 255)/256, 256>>>((const float4*)w_qkv, (float4*)wq_p, 1152*384/4);
    round_kernel<<<(384*384/4 + 255)/256, 256>>>((const float4*)w_out, (float4*)wo_p, 384*384/4);
    ridx_kernel<<<10, 256>>>();

    const int SMEM = 98304;
    cudaFuncSetAttribute(mma_qkv_kernel, cudaFuncAttributeMaxDynamicSharedMemorySize, SMEM);
    cudaFuncSetAttribute(mma_out_kernel, cudaFuncAttributeMaxDynamicSharedMemorySize, SMEM);

    mma_qkv_kernel<<<dim3(9, 784), 256, SMEM>>>(b_qkv);
    attn_kernel<<<24576, 128>>>(mask, table);
    mma_out_kernel<<<dim3(3, 784), 256, SMEM>>>(b_out, out);
}

// round 8
// speedup vs baseline: 2.8581x; 1.0625x over previous
#include <cuda_runtime.h>
#include <math.h>
#include <stdint.h>

#define NROWS 100352

__device__ float g_q[(size_t)24576*1568];   // [B*H, 49, 32], pre-scaled, tf32-rounded
__device__ float g_k[(size_t)24576*1568];
__device__ float g_v[(size_t)24576*1568];
__device__ float g_att[(size_t)NROWS*384];  // tf32-rounded
__device__ float g_hid[(size_t)NROWS*384];  // tf32-rounded hidden
__device__ float g_wq[1152*384];            // tf32-rounded w_qkv
__device__ float g_wo[384*384];             // tf32-rounded w_out
__device__ int   g_ridx[2401];              // rel-pos index * 12

__device__ __forceinline__ uint32_t smem_u32(const void* p) {
    uint32_t a;
    asm("{ .reg .u64 t; cvta.to.shared.u64 t, %1; cvt.u32.u64 %0, t; }" : "=r"(a) : "l"(p));
    return a;
}
__device__ __forceinline__ uint32_t f2tf(float x) {
    uint32_t r; asm("cvt.rna.tf32.f32 %0, %1;" : "=r"(r) : "f"(x)); return r;
}
__device__ __forceinline__ float tf32f(float x) { return __uint_as_float(f2tf(x)); }
__device__ __forceinline__ void mma8(float* c, const uint32_t* a, uint32_t b0, uint32_t b1) {
    asm volatile("mma.sync.aligned.m16n8k8.row.col.f32.tf32.tf32.f32 "
        "{%0,%1,%2,%3}, {%4,%5,%6,%7}, {%8,%9}, {%0,%1,%2,%3};"
        : "+f"(c[0]), "+f"(c[1]), "+f"(c[2]), "+f"(c[3])
        : "r"(a[0]), "r"(a[1]), "r"(a[2]), "r"(a[3]), "r"(b0), "r"(b1));
}
__device__ __forceinline__ void ldsm4(uint32_t* r, uint32_t a) {
    asm volatile("ldmatrix.sync.aligned.m8n8.x4.shared.b16 {%0,%1,%2,%3}, [%4];"
        : "=r"(r[0]), "=r"(r[1]), "=r"(r[2]), "=r"(r[3]) : "r"(a));
}
__device__ __forceinline__ void ldsm2(uint32_t* r, uint32_t a) {
    asm volatile("ldmatrix.sync.aligned.m8n8.x2.shared.b16 {%0,%1}, [%2];"
        : "=r"(r[0]), "=r"(r[1]) : "r"(a));
}
__device__ __forceinline__ void cp16(uint32_t s, const float* g) {
    asm volatile("cp.async.cg.shared.global [%0], [%1], 16;" :: "r"(s), "l"(g));
}

// ---------------------------------------------------------------------------
// Prepass: tf32-round arrays + ridx table
// ---------------------------------------------------------------------------
__global__ void round_kernel(const float4* __restrict__ src, float4* __restrict__ dst, int n4) {
    int i = blockIdx.x * blockDim.x + threadIdx.x;
    if (i < n4) {
        float4 v = src[i];
        v.x = tf32f(v.x); v.y = tf32f(v.y); v.z = tf32f(v.z); v.w = tf32f(v.w);
        dst[i] = v;
    }
}
__global__ void ridx_kernel() {
    int e = blockIdx.x * blockDim.x + threadIdx.x;
    if (e < 2401) {
        int i = e / 49, j = e - i * 49;
        int yi = i / 7, xi = i - yi * 7, yj = j / 7, xj = j - yj * 7;
        g_ridx[e] = ((yi - yj + 6) * 13 + (xi - xj + 6)) * 12;
    }
}

// ===========================================================================
// TF32 GEMM: C[128x128] of A[M,384] @ W[N,384]^T; inputs pre-rounded.
// 8 warps, BK=32, 3-stage cp.async, XOR-swizzled tiles, ldmatrix frag loads.
// ===========================================================================
__device__ __forceinline__ void gemm_tf32(const float* __restrict__ A,
                                          const float* __restrict__ W,
                                          int bm, int bn, float acc[4][4][4])
{
    extern __shared__ float sm[];
    const int tid = threadIdx.x;
    const int l = tid & 31, l7 = l & 7;
    const int wm = (tid >> 5) >> 2, wn = (tid >> 5) & 3;

    const int prow = tid >> 1, pc = (tid & 1) * 16;
    const float* ga = A + (size_t)(bm + prow) * 384 + pc;
    const float* gb = W + (size_t)(bn + prow) * 384 + pc;
    const uint32_t swz = (uint32_t)((prow & 7) << 2);
    const uint32_t sa0 = smem_u32(sm) + (uint32_t)prow * 128;
    const uint32_t sb0 = sa0 + 49152;

#pragma unroll
    for (int mi = 0; mi < 4; mi++)
#pragma unroll
        for (int nj = 0; nj < 4; nj++)
#pragma unroll
            for (int q = 0; q < 4; q++) acc[mi][nj][q] = 0.f;

#define ISSUE(KT) do {                                                        \
    uint32_t off = (uint32_t)((KT) % 3) * 16384;                              \
    const float* pa = ga + (KT) * 32;                                         \
    const float* pb = gb + (KT) * 32;                                         \
    _Pragma("unroll")                                                         \
    for (int u = 0; u < 4; u++) {                                             \
        uint32_t c = ((uint32_t)(pc + 4 * u) ^ swz) * 4;                      \
        cp16(sa0 + off + c, pa + 4 * u);                                      \
        cp16(sb0 + off + c, pb + 4 * u);                                      \
    }                                                                         \
    asm volatile("cp.async.commit_group;" ::: "memory");                      \
} while (0)

    ISSUE(0); ISSUE(1);

    // ldmatrix per-lane row byte-offsets (row&7 == l7 for all tiles)
    const int ah = (l >> 3) & 1, bh2 = l >> 4;   // A: +8 rows, B: +8 rows selectors
    uint32_t a_rb[4], b_rb[2];
#pragma unroll
    for (int mi = 0; mi < 4; mi++)
        a_rb[mi] = (uint32_t)((wm * 64 + mi * 16 + l7 + ah * 8) * 128);
#pragma unroll
    for (int p = 0; p < 2; p++)
        b_rb[p] = (uint32_t)((wn * 32 + p * 16 + l7 + bh2 * 8) * 128);
    const uint32_t smbase = smem_u32(sm);

    for (int kt = 0; kt < 12; kt++) {
        if (kt < 11) asm volatile("cp.async.wait_group 1;" ::: "memory");
        else         asm volatile("cp.async.wait_group 0;" ::: "memory");
        __syncthreads();
        if (kt < 10) ISSUE(kt + 2);

        const uint32_t bA = smbase + (uint32_t)(kt % 3) * 16384;
        const uint32_t bB = bA + 49152;
#pragma unroll
        for (int kc = 0; kc < 4; kc++) {
            const uint32_t uA = (uint32_t)(((2 * kc + bh2) ^ l7) << 4);
            const uint32_t uB = (uint32_t)(((2 * kc + ah) ^ l7) << 4);
            uint32_t af[4][4], b0[4], b1[4];
#pragma unroll
            for (int mi = 0; mi < 4; mi++) ldsm4(af[mi], bA + a_rb[mi] + uA);
            ldsm4(b0, bB + b_rb[0] + uB);
            ldsm4(b1, bB + b_rb[1] + uB);
#pragma unroll
            for (int mi = 0; mi < 4; mi++) {
                mma8(acc[mi][0], af[mi], b0[0], b0[1]);
                mma8(acc[mi][1], af[mi], b0[2], b0[3]);
                mma8(acc[mi][2], af[mi], b1[0], b1[1]);
                mma8(acc[mi][3], af[mi], b1[2], b1[3]);
            }
        }
    }
#undef ISSUE
}

// ---------------------------------------------------------------------------
__global__ void __launch_bounds__(256, 2)
mma_qkv_kernel(const float* __restrict__ bias)
{
    int tid = threadIdx.x;
    int bm = blockIdx.y * 128, bn = blockIdx.x * 128;
    float acc[4][4][4];
    gemm_tf32(g_hid, g_wq, bm, bn, acc);

    int l = tid & 31;
    int wm = (tid >> 5) >> 2, wn = (tid >> 5) & 3;
    int part = bn / 384;
    int h = ((bn % 384) + wn * 32) >> 5;
    const float scl = (part == 0) ? 0.17677669529663687f : 1.0f;
    float* base = (part == 0) ? g_q : (part == 1) ? g_k : g_v;

#pragma unroll
    for (int mi = 0; mi < 4; mi++)
#pragma unroll
        for (int nj = 0; nj < 4; nj++) {
            int n = bn + wn * 32 + nj * 8 + (l & 3) * 2;
            int d = nj * 8 + (l & 3) * 2;
            float b0 = bias[n], b1 = bias[n + 1];
#pragma unroll
            for (int rh = 0; rh < 2; rh++) {
                int row = bm + wm * 64 + mi * 16 + (l >> 2) + rh * 8;
                int bb = row / 49, ss = row - bb * 49;
                size_t o = (((size_t)(bb * 12 + h) * 49 + ss) << 5) + d;
                *(float2*)&base[o] =
                    make_float2(tf32f((acc[mi][nj][rh*2] + b0) * scl),
                                tf32f((acc[mi][nj][rh*2+1] + b1) * scl));
            }
        }
}

// ---------------------------------------------------------------------------
__global__ void __launch_bounds__(256, 2)
mma_out_kernel(const float* __restrict__ bias, float* __restrict__ C)
{
    int tid = threadIdx.x;
    int bm = blockIdx.y * 128, bn = blockIdx.x * 128;
    float acc[4][4][4];
    gemm_tf32(g_att, g_wo, bm, bn, acc);

    int l = tid & 31;
    int wm = (tid >> 5) >> 2, wn = (tid >> 5) & 3;
#pragma unroll
    for (int mi = 0; mi < 4; mi++)
#pragma unroll
        for (int nj = 0; nj < 4; nj++) {
            int n = bn + wn * 32 + nj * 8 + (l & 3) * 2;
            float b0 = bias[n], b1 = bias[n + 1];
#pragma unroll
            for (int rh = 0; rh < 2; rh++) {
                int row = bm + wm * 64 + mi * 16 + (l >> 2) + rh * 8;
                *(float2*)&C[(size_t)row * 384 + n] =
                    make_float2(acc[mi][nj][rh*2] + b0, acc[mi][nj][rh*2+1] + b1);
            }
        }
}

// ---------------------------------------------------------------------------
// Attention: one CTA per (b,h). ldmatrix fragment loads for Q/K/P.
// ---------------------------------------------------------------------------
__global__ void __launch_bounds__(128)
attn_kernel(const float* __restrict__ mask, const float* __restrict__ table)
{
    __shared__ float qs[64 * 36];
    __shared__ float ks[56 * 36];
    __shared__ float vs[56 * 40];
    __shared__ float amb[64 * 60];  // bias+mask, then P (tf32-rounded)

    int bh = blockIdx.x;
    int b = bh / 12, h = bh - b * 12;
    int tid = threadIdx.x, w = tid >> 5, l = tid & 31, g = l >> 2, t = l & 3;
    const int l7 = l & 7, ah = (l >> 3) & 1, bh2 = l >> 4;

    const float4* qg = (const float4*)(g_q + (size_t)bh * 1568);
    const float4* kg = (const float4*)(g_k + (size_t)bh * 1568);
    const float4* vg = (const float4*)(g_v + (size_t)bh * 1568);
    for (int e = tid; e < 392; e += 128) {
        int i = e >> 3, c = (e & 7) * 4;
        *(float4*)&qs[i * 36 + c] = qg[e];
        *(float4*)&ks[i * 36 + c] = kg[e];
        *(float4*)&vs[i * 40 + c] = vg[e];
    }
    for (int e = tid; e < 280; e += 128) vs[1960 + e] = 0.f;
    const float* mrow = mask + (size_t)b * 2401;
    for (int e = tid; e < 2401; e += 128) {
        int i = e / 49, j = e - i * 49;
        amb[i * 60 + j] = mrow[e] + table[g_ridx[e] + h];
    }
    __syncthreads();

    const uint32_t qsb = smem_u32(qs), ksb = smem_u32(ks), ambb = smem_u32(amb);
    const uint32_t qrow = (uint32_t)((w * 16 + l7 + ah * 8) * 144);
    uint32_t krow[3];
#pragma unroll
    for (int p = 0; p < 3; p++)
        krow[p] = (uint32_t)((p * 16 + l7 + bh2 * 8) * 144);
    const uint32_t krow6 = (uint32_t)((48 + l7) * 144);

    // QK^T
    float s[7][4];
#pragma unroll
    for (int T = 0; T < 7; T++) { s[T][0]=0.f; s[T][1]=0.f; s[T][2]=0.f; s[T][3]=0.f; }
    const int rA = w * 16 + g;
#pragma unroll
    for (int kc = 0; kc < 4; kc++) {
        uint32_t a[4];
        ldsm4(a, qsb + qrow + (uint32_t)((2 * kc + bh2) << 4));
        uint32_t uB = (uint32_t)((2 * kc + ah) << 4);
#pragma unroll
        for (int p = 0; p < 3; p++) {
            uint32_t kb[4];
            ldsm4(kb, ksb + krow[p] + uB);
            mma8(s[2*p],   a, kb[0], kb[1]);
            mma8(s[2*p+1], a, kb[2], kb[3]);
        }
        uint32_t k2[2];
        ldsm2(k2, ksb + krow6 + uB);
        mma8(s[6], a, k2[0], k2[1]);
    }
    // + bias + mask, j>=49 -> -inf
#pragma unroll
    for (int T = 0; T < 7; T++) {
        int j0 = T * 8 + 2 * t;
        float2 m0 = *(const float2*)&amb[rA * 60 + j0];
        float2 m1 = *(const float2*)&amb[(rA + 8) * 60 + j0];
        s[T][0] = (j0 < 49)     ? s[T][0] + m0.x : -1e30f;
        s[T][1] = (j0 + 1 < 49) ? s[T][1] + m0.y : -1e30f;
        s[T][2] = (j0 < 49)     ? s[T][2] + m1.x : -1e30f;
        s[T][3] = (j0 + 1 < 49) ? s[T][3] + m1.y : -1e30f;
    }
    // softmax (rows rA, rA+8)
    float mA = -1e30f, mB = -1e30f;
#pragma unroll
    for (int T = 0; T < 7; T++) {
        mA = fmaxf(mA, fmaxf(s[T][0], s[T][1]));
        mB = fmaxf(mB, fmaxf(s[T][2], s[T][3]));
    }
    mA = fmaxf(mA, __shfl_xor_sync(~0u, mA, 1)); mA = fmaxf(mA, __shfl_xor_sync(~0u, mA, 2));
    mB = fmaxf(mB, __shfl_xor_sync(~0u, mB, 1)); mB = fmaxf(mB, __shfl_xor_sync(~0u, mB, 2));
    float dA = 0.f, dB = 0.f;
#pragma unroll
    for (int T = 0; T < 7; T++) {
        s[T][0] = __expf(s[T][0] - mA); s[T][1] = __expf(s[T][1] - mA);
        s[T][2] = __expf(s[T][2] - mB); s[T][3] = __expf(s[T][3] - mB);
        dA += s[T][0] + s[T][1]; dB += s[T][2] + s[T][3];
    }
    dA += __shfl_xor_sync(~0u, dA, 1); dA += __shfl_xor_sync(~0u, dA, 2);
    dB += __shfl_xor_sync(~0u, dB, 1); dB += __shfl_xor_sync(~0u, dB, 2);
    float iA = 1.f / dA, iB = 1.f / dB;
#pragma unroll
    for (int T = 0; T < 7; T++) {
        int j0 = T * 8 + 2 * t;
        *(float2*)&amb[rA * 60 + j0] =
            make_float2(tf32f(s[T][0] * iA), tf32f(s[T][1] * iA));
        *(float2*)&amb[(rA + 8) * 60 + j0] =
            make_float2(tf32f(s[T][2] * iB), tf32f(s[T][3] * iB));
    }
    __syncwarp();

    // PV: P frags via ldmatrix, V scalar (transposed access)
    const uint32_t prow = (uint32_t)((w * 16 + l7 + ah * 8) * 240);
    float o[4][4];
#pragma unroll
    for (int nj = 0; nj < 4; nj++) { o[nj][0]=0.f; o[nj][1]=0.f; o[nj][2]=0.f; o[nj][3]=0.f; }
#pragma unroll
    for (int kc = 0; kc < 7; kc++) {
        uint32_t a[4];
        ldsm4(a, ambb + prow + (uint32_t)((2 * kc + bh2) << 4));
        int c = kc * 8 + t;
#pragma unroll
        for (int nj = 0; nj < 4; nj++)
            mma8(o[nj], a, __float_as_uint(vs[c * 40 + nj * 8 + g]),
                 __float_as_uint(vs[(c + 4) * 40 + nj * 8 + g]));
    }
    float* ap = g_att + (size_t)b * 18816 + h * 32;
#pragma unroll
    for (int nj = 0; nj < 4; nj++) {
        int d = nj * 8 + 2 * t;
        if (rA < 49)
            *(float2*)&ap[(size_t)rA * 384 + d] =
                make_float2(tf32f(o[nj][0]), tf32f(o[nj][1]));
        if (rA + 8 < 49)
            *(float2*)&ap[(size_t)(rA + 8) * 384 + d] =
                make_float2(tf32f(o[nj][2]), tf32f(o[nj][3]));
    }
}

// ---------------------------------------------------------------------------
extern "C" void kernel_launch(void* const* d_in, const int* in_sizes, int n_in,
                              void* d_out, int out_size)
{
    const float* hidden = (const float*)d_in[0];
    const float* mask   = (const float*)d_in[1];
    const float* w_qkv  = (const float*)d_in[2];
    const float* b_qkv  = (const float*)d_in[3];
    const float* w_out  = (const float*)d_in[4];
    const float* b_out  = (const float*)d_in[5];
    const float* table  = (const float*)d_in[6];
    float* out = (float*)d_out;

    float* hid_p; cudaGetSymbolAddress((void**)&hid_p, g_hid);
    float* wq_p;  cudaGetSymbolAddress((void**)&wq_p,  g_wq);
    float* wo_p;  cudaGetSymbolAddress((void**)&wo_p,  g_wo);

    round_kernel<<<(NROWS*384/4 + 255)/256, 256>>>((const float4*)hidden, (float4*)hid_p, NROWS*384/4);
    round_kernel<<<(1152*384/4 + 255)/256, 256>>>((const float4*)w_qkv, (float4*)wq_p, 1152*384/4);
    round_kernel<<<(384*384/4 + 255)/256, 256>>>((const float4*)w_out, (float4*)wo_p, 384*384/4);
    ridx_kernel<<<10, 256>>>();

    const int SMEM = 98304;
    cudaFuncSetAttribute(mma_qkv_kernel, cudaFuncAttributeMaxDynamicSharedMemorySize, SMEM);
    cudaFuncSetAttribute(mma_out_kernel, cudaFuncAttributeMaxDynamicSharedMemorySize, SMEM);

    mma_qkv_kernel<<<dim3(9, 784), 256, SMEM>>>(b_qkv);
    attn_kernel<<<24576, 128>>>(mask, table);
    mma_out_kernel<<<dim3(3, 784), 256, SMEM>>>(b_out, out);
}